// round 4
// baseline (speedup 1.0000x reference)
#include <cuda_runtime.h>
#include <math.h>

#define D 128
#define MAX_NDST 50000
#define MAX_NSRC 100000
#define MAX_E    600000
#define SCAN_B   512

typedef unsigned long long ull;

// Scratch (static device globals -- no allocation allowed)
__device__ __align__(16) float g_a_dst[MAX_NDST * D];   // feat_dst @ W1[:, :128]^T + b1
__device__ __align__(16) float g_b_src[MAX_NSRC * D];   // feat_src @ W1[:, 128:]^T
__device__ __align__(16) float g_neigh[MAX_NDST * D];   // softmax-weighted aggregation
__device__ int g_cnt[MAX_NDST];                          // per-dst degree
__device__ int g_off[MAX_NDST + 1];                      // CSR offsets
__device__ int g_cur[MAX_NDST];                          // scatter cursors
__device__ int g_srcs[MAX_E];                            // CSR: src id per slot
__device__ int g_part[256];                              // scan partials

// ---------------------------------------------------------------------------
// fast tanh (MUFU.TANH, sm_75+) and packed f32x2 helpers (sm_100+)
// ---------------------------------------------------------------------------
__device__ __forceinline__ float tanha(float x) {
    float y;
    asm("tanh.approx.f32 %0, %1;" : "=f"(y) : "f"(x));
    return y;
}

#define FMA2(d, a, b) \
    asm("fma.rn.f32x2 %0, %1, %2, %3;" : "=l"(d) : "l"(a), "l"(b), "l"(d))
#define PACK2(out, x) \
    asm("mov.b64 %0, {%1, %2};" : "=l"(out) : "f"(x), "f"(x))
#define UNPACK2(lo, hi, in) \
    asm("mov.b64 {%0, %1}, %2;" : "=f"(lo), "=f"(hi) : "l"(in))

// ---------------------------------------------------------------------------
// CSR build: zero counts -> count -> scan(3) -> scatter
// ---------------------------------------------------------------------------
__global__ void zero_cnt_kernel(int n) {
    int i = blockIdx.x * blockDim.x + threadIdx.x;
    if (i < n) g_cnt[i] = 0;
}

__global__ void count_kernel(const int* __restrict__ ed, int E) {
    int e = blockIdx.x * blockDim.x + threadIdx.x;
    if (e < E) atomicAdd(&g_cnt[ed[e]], 1);
}

__device__ __forceinline__ int warp_incl_scan(int v, int lane) {
#pragma unroll
    for (int o = 1; o < 32; o <<= 1) {
        int t = __shfl_up_sync(0xFFFFFFFFu, v, o);
        if (lane >= o) v += t;
    }
    return v;
}

// per-block sums of g_cnt
__global__ void __launch_bounds__(SCAN_B) scan1_kernel(int n) {
    __shared__ int wsum[SCAN_B / 32];
    int tid  = threadIdx.x;
    int lane = tid & 31;
    int wid  = tid >> 5;
    int i = blockIdx.x * SCAN_B + tid;
    int v = (i < n) ? g_cnt[i] : 0;
#pragma unroll
    for (int o = 16; o; o >>= 1) v += __shfl_xor_sync(0xFFFFFFFFu, v, o);
    if (lane == 0) wsum[wid] = v;
    __syncthreads();
    if (wid == 0) {
        int s = (lane < SCAN_B / 32) ? wsum[lane] : 0;
#pragma unroll
        for (int o = 16; o; o >>= 1) s += __shfl_xor_sync(0xFFFFFFFFu, s, o);
        if (lane == 0) g_part[blockIdx.x] = s;
    }
}

// exclusive scan of partials (single block, nb <= 128) + write g_off[n] = E
__global__ void scan2_kernel(int nb, int n, int E) {
    __shared__ int sh[128];
    int tid = threadIdx.x;
    int v = (tid < nb) ? g_part[tid] : 0;
    sh[tid] = v;
    __syncthreads();
#pragma unroll
    for (int o = 1; o < 128; o <<= 1) {
        int t = (tid >= o) ? sh[tid - o] : 0;
        __syncthreads();
        sh[tid] += t;
        __syncthreads();
    }
    if (tid < nb) g_part[tid] = sh[tid] - v;   // exclusive
    if (tid == 0) g_off[n] = E;
}

// block-local exclusive scan + partial offset -> g_off, g_cur
__global__ void __launch_bounds__(SCAN_B) scan3_kernel(int n) {
    __shared__ int wsum[SCAN_B / 32];
    int tid  = threadIdx.x;
    int lane = tid & 31;
    int wid  = tid >> 5;
    int i = blockIdx.x * SCAN_B + tid;
    int v = (i < n) ? g_cnt[i] : 0;
    int incl = warp_incl_scan(v, lane);
    if (lane == 31) wsum[wid] = incl;
    __syncthreads();
    if (wid == 0) {
        int s = (lane < SCAN_B / 32) ? wsum[lane] : 0;
        int si = warp_incl_scan(s, lane);
        if (lane < SCAN_B / 32) wsum[lane] = si - s;  // exclusive warp offsets
    }
    __syncthreads();
    int excl = incl - v + wsum[wid] + g_part[blockIdx.x];
    if (i < n) {
        g_off[i] = excl;
        g_cur[i] = excl;
    }
}

__global__ void scatter_kernel(const int* __restrict__ es,
                               const int* __restrict__ ed, int E) {
    int e = blockIdx.x * blockDim.x + threadIdx.x;
    if (e < E) {
        int pos = atomicAdd(&g_cur[ed[e]], 1);
        g_srcs[pos] = es[e];
    }
}

// ---------------------------------------------------------------------------
// Tiled fp32 GEMM with packed FFMA2 (fma.rn.f32x2, sm_100+):
//   C[m, n] = act( sum_k A[m,k] * W[n, wbase + k] + bias[n] )
//   TWO=true: K=256 split across A1 (W cols 0..127) and A2 (W cols 128..255).
// Block: 256 threads computes 128(M) x 128(N) tile; thread tile 8x8 with
// accumulator pairs along M (acc2[rowpair][col], FFMA2 per pair). BK = 32.
// ---------------------------------------------------------------------------
template <bool TWO, bool RELU>
__global__ void __launch_bounds__(256) gemm_kernel(
    const float* __restrict__ A1,
    const float* __restrict__ A2,
    const float* __restrict__ W, int ldw, int wbase,
    const float* __restrict__ bias,
    float* __restrict__ C, int M)
{
    __shared__ float As[32][132];   // [k][m]
    __shared__ float Bs[32][132];   // [k][n]

    const int tid = threadIdx.x;
    const int tm  = tid >> 4;       // 0..15 -> rows tm*8 .. tm*8+7
    const int tn  = tid & 15;       // 0..15 -> cols tn*8 .. tn*8+7
    const int m0  = blockIdx.x * 128;

    ull acc[4][8];                  // [row-pair][col]; pair = rows (2r, 2r+1)
#pragma unroll
    for (int r = 0; r < 4; r++)
#pragma unroll
        for (int j = 0; j < 8; j++) acc[r][j] = 0ull;

    const int nkt = TWO ? 8 : 4;
    for (int kt = 0; kt < nkt; kt++) {
        const int wcol = wbase + kt * 32;
        const float* A = (TWO && kt >= 4) ? A2 : A1;
        const int ak0  = (TWO && kt >= 4) ? (kt - 4) * 32 : kt * 32;

        // --- load A tile (128 m x 32 k) transposed into As[k][m] ---
#pragma unroll
        for (int t = 0; t < 4; t++) {
            int idx = tid + t * 256;          // 0..1023 float4 slots
            int row = idx >> 3;               // 0..127
            int c4  = idx & 7;                // 0..7
            int m   = m0 + row;
            if (m >= M) m = M - 1;            // clamp (safe duplicate)
            float4 v = *(const float4*)(A + (size_t)m * D + ak0 + c4 * 4);
            As[c4 * 4 + 0][row] = v.x;
            As[c4 * 4 + 1][row] = v.y;
            As[c4 * 4 + 2][row] = v.z;
            As[c4 * 4 + 3][row] = v.w;
        }
        // --- load W tile (128 n x 32 k) into Bs[k][n] ---
#pragma unroll
        for (int t = 0; t < 4; t++) {
            int idx = tid + t * 256;
            int n   = idx >> 3;
            int c4  = idx & 7;
            float4 v = *(const float4*)(W + (size_t)n * ldw + wcol + c4 * 4);
            Bs[c4 * 4 + 0][n] = v.x;
            Bs[c4 * 4 + 1][n] = v.y;
            Bs[c4 * 4 + 2][n] = v.z;
            Bs[c4 * 4 + 3][n] = v.w;
        }
        __syncthreads();

#pragma unroll
        for (int k = 0; k < 32; k++) {
            // A row pairs: (m, m+1) packed -- consecutive floats in As[k]
            const ull* arow = (const ull*)&As[k][tm * 8];
            ull ap0 = arow[0], ap1 = arow[1], ap2 = arow[2], ap3 = arow[3];
            // B values, broadcast-packed (w, w)
            float4 b0 = *(const float4*)&Bs[k][tn * 8];
            float4 b1 = *(const float4*)&Bs[k][tn * 8 + 4];
            ull bb[8];
            PACK2(bb[0], b0.x); PACK2(bb[1], b0.y);
            PACK2(bb[2], b0.z); PACK2(bb[3], b0.w);
            PACK2(bb[4], b1.x); PACK2(bb[5], b1.y);
            PACK2(bb[6], b1.z); PACK2(bb[7], b1.w);
#pragma unroll
            for (int j = 0; j < 8; j++) {
                FMA2(acc[0][j], ap0, bb[j]);
                FMA2(acc[1][j], ap1, bb[j]);
                FMA2(acc[2][j], ap2, bb[j]);
                FMA2(acc[3][j], ap3, bb[j]);
            }
        }
        __syncthreads();
    }

    // --- epilogue ---
    const int n0 = tn * 8;
    float bv[8] = {0.f, 0.f, 0.f, 0.f, 0.f, 0.f, 0.f, 0.f};
    if (bias) {
        float4 q0 = *(const float4*)(bias + n0);
        float4 q1 = *(const float4*)(bias + n0 + 4);
        bv[0] = q0.x; bv[1] = q0.y; bv[2] = q0.z; bv[3] = q0.w;
        bv[4] = q1.x; bv[5] = q1.y; bv[6] = q1.z; bv[7] = q1.w;
    }
#pragma unroll
    for (int r = 0; r < 4; r++) {
        float lo[8], hi[8];
#pragma unroll
        for (int j = 0; j < 8; j++) {
            UNPACK2(lo[j], hi[j], acc[r][j]);
            lo[j] += bv[j];
            hi[j] += bv[j];
            if (RELU) { lo[j] = fmaxf(lo[j], 0.f); hi[j] = fmaxf(hi[j], 0.f); }
        }
        int m = m0 + tm * 8 + 2 * r;
        if (m < M) {
            float* crow = C + (size_t)m * D + n0;
            *(float4*)(crow)     = make_float4(lo[0], lo[1], lo[2], lo[3]);
            *(float4*)(crow + 4) = make_float4(lo[4], lo[5], lo[6], lo[7]);
        }
        if (m + 1 < M) {
            float* crow = C + (size_t)(m + 1) * D + n0;
            *(float4*)(crow)     = make_float4(hi[0], hi[1], hi[2], hi[3]);
            *(float4*)(crow + 4) = make_float4(hi[4], hi[5], hi[6], hi[7]);
        }
    }
}

// ---------------------------------------------------------------------------
// Fused attention: one warp per dst node, single pass over its CSR edges.
//   score_e = W2 . tanh(a_dst[d] + b_src[s_e]) + b2   (no segment-max needed:
//             |score| <= sum|W2| ~ 28, exp cannot overflow)
//   neigh[d] = (sum_e exp(score_e) * feat_src[s_e]) / (sum_e exp(score_e))
// Next-index software pipelining hides the idx->row dependent-load chain.
// ---------------------------------------------------------------------------
__global__ void __launch_bounds__(256) fused_attn_kernel(
    const float* __restrict__ feat_src,
    const float* __restrict__ W2,
    const float* __restrict__ b2,
    int ndst)
{
    int w    = (blockIdx.x * blockDim.x + threadIdx.x) >> 5;
    int lane = threadIdx.x & 31;
    if (w >= ndst) return;

    int beg = g_off[w];
    int end = g_off[w + 1];
    float4* nrow = (float4*)(g_neigh + (size_t)w * D);

    if (beg == end) {                 // 0-degree: neigh = 0 (matches ref)
        nrow[lane] = make_float4(0.f, 0.f, 0.f, 0.f);
        return;
    }

    float4 ad = ((const float4*)(g_a_dst + (size_t)w * D))[lane];
    float4 w2 = ((const float4*)W2)[lane];
    float b2v = b2[0];

    float denom = 0.0f;
    float4 acc = make_float4(0.f, 0.f, 0.f, 0.f);

    int s = __ldg(&g_srcs[beg]);
    for (int i = beg; i < end; i++) {
        int s_next = (i + 1 < end) ? __ldg(&g_srcs[i + 1]) : 0;
        float4 bs = ((const float4*)(g_b_src + (size_t)s * D))[lane];
        float4 m  = ((const float4*)(feat_src + (size_t)s * D))[lane];

        float p = tanha(ad.x + bs.x) * w2.x
                + tanha(ad.y + bs.y) * w2.y
                + tanha(ad.z + bs.z) * w2.z
                + tanha(ad.w + bs.w) * w2.w;
#pragma unroll
        for (int o = 16; o; o >>= 1) p += __shfl_xor_sync(0xFFFFFFFFu, p, o);

        float ex = __expf(p + b2v);
        denom += ex;
        acc.x = fmaf(ex, m.x, acc.x);
        acc.y = fmaf(ex, m.y, acc.y);
        acc.z = fmaf(ex, m.z, acc.z);
        acc.w = fmaf(ex, m.w, acc.w);
        s = s_next;
    }

    float inv = 1.0f / denom;
    acc.x *= inv; acc.y *= inv; acc.z *= inv; acc.w *= inv;
    nrow[lane] = acc;
}

// ---------------------------------------------------------------------------
// Launcher
// ---------------------------------------------------------------------------
extern "C" void kernel_launch(void* const* d_in, const int* in_sizes, int n_in,
                              void* d_out, int out_size)
{
    const float* feat_src = (const float*)d_in[0];
    const float* feat_dst = (const float*)d_in[1];
    const float* W1       = (const float*)d_in[2];
    const float* b1       = (const float*)d_in[3];
    const float* W2       = (const float*)d_in[4];
    const float* b2       = (const float*)d_in[5];
    const float* Wfc      = (const float*)d_in[6];
    const float* bfc      = (const float*)d_in[7];
    const int*   es       = (const int*)d_in[8];
    const int*   ed       = (const int*)d_in[9];

    const int NSRC = in_sizes[0] / D;
    const int NDST = in_sizes[1] / D;
    const int E    = in_sizes[8];
    float* out = (float*)d_out;

    void *p_a, *p_b, *p_n;
    cudaGetSymbolAddress(&p_a, g_a_dst);
    cudaGetSymbolAddress(&p_b, g_b_src);
    cudaGetSymbolAddress(&p_n, g_neigh);
    float* a_dst = (float*)p_a;
    float* b_src = (float*)p_b;
    float* neigh = (float*)p_n;

    // --- CSR build ---
    zero_cnt_kernel<<<(NDST + 255) / 256, 256>>>(NDST);
    count_kernel<<<(E + 255) / 256, 256>>>(ed, E);
    int nb = (NDST + SCAN_B - 1) / SCAN_B;     // <= 128
    scan1_kernel<<<nb, SCAN_B>>>(NDST);
    scan2_kernel<<<1, 128>>>(nb, NDST, E);
    scan3_kernel<<<nb, SCAN_B>>>(NDST);
    scatter_kernel<<<(E + 255) / 256, 256>>>(es, ed, E);

    // --- node GEMMs (FFMA2 path) ---
    gemm_kernel<false, false><<<(NDST + 127) / 128, 256>>>(
        feat_dst, nullptr, W1, 2 * D, 0, b1, a_dst, NDST);
    gemm_kernel<false, false><<<(NSRC + 127) / 128, 256>>>(
        feat_src, nullptr, W1, 2 * D, D, nullptr, b_src, NSRC);

    // --- fused edge softmax + aggregation (single pass) ---
    fused_attn_kernel<<<(NDST * 32 + 255) / 256, 256>>>(feat_src, W2, b2, NDST);

    // --- out = relu( [feat_dst, neigh] @ Wfc^T + bfc ) ---
    gemm_kernel<true, true><<<(NDST + 127) / 128, 256>>>(
        feat_dst, neigh, Wfc, 2 * D, 0, bfc, out, NDST);
}

// round 9
// speedup vs baseline: 1.5473x; 1.5473x over previous
#include <cuda_runtime.h>
#include <cuda_bf16.h>
#include <cstdint>
#include <cstring>
#include <math.h>

#define D 128
#define MAX_NDST 50000
#define MAX_NSRC 100000
#define MAX_E    600000
#define SCAN_B   512

// Scratch (static device globals -- no allocation allowed)
__device__ __align__(16) float g_a_dst[MAX_NDST * D];   // feat_dst @ W1[:, :128]^T + b1
__device__ __align__(16) float g_b_src[MAX_NSRC * D];   // feat_src @ W1[:, 128:]^T
__device__ __align__(16) float g_neigh[MAX_NDST * D];   // softmax-weighted aggregation
__device__ int g_cnt[MAX_NDST];
__device__ int g_off[MAX_NDST + 1];
__device__ int g_cur[MAX_NDST];
__device__ int g_srcs[MAX_E];
__device__ int g_part[256];

// ---------------------------------------------------------------------------
// helpers
// ---------------------------------------------------------------------------
__device__ __forceinline__ float tanha(float x) {
    float y;
    asm("tanh.approx.f32 %0, %1;" : "=f"(y) : "f"(x));
    return y;
}

__device__ __forceinline__ uint32_t s2u(const void* p) {
    uint32_t a;
    asm("{ .reg .u64 t; cvta.to.shared.u64 t, %1; cvt.u32.u64 %0, t; }"
        : "=r"(a) : "l"(p));
    return a;
}

__device__ __forceinline__ void ldsm_x4(uint32_t* r, uint32_t addr) {
    asm volatile("ldmatrix.sync.aligned.m8n8.x4.shared.b16 {%0,%1,%2,%3}, [%4];"
        : "=r"(r[0]), "=r"(r[1]), "=r"(r[2]), "=r"(r[3]) : "r"(addr));
}

// D[16x8] += A[16x16] * B[16x8] (bf16 in, fp32 acc)
__device__ __forceinline__ void mma16816(float* c, const uint32_t* a, const uint32_t* b) {
    asm volatile("mma.sync.aligned.m16n8k16.row.col.f32.bf16.bf16.f32 "
        "{%0,%1,%2,%3}, {%4,%5,%6,%7}, {%8,%9}, {%0,%1,%2,%3};"
        : "+f"(c[0]), "+f"(c[1]), "+f"(c[2]), "+f"(c[3])
        : "r"(a[0]), "r"(a[1]), "r"(a[2]), "r"(a[3]), "r"(b[0]), "r"(b[1]));
}

__device__ __forceinline__ uint32_t pack_bf16(float a, float b) {
    __nv_bfloat162 t = __floats2bfloat162_rn(a, b);
    uint32_t r;
    memcpy(&r, &t, 4);
    return r;
}

__device__ __forceinline__ uint32_t pack2h(__nv_bfloat16 a, __nv_bfloat16 b) {
    uint16_t ua, ub;
    memcpy(&ua, &a, 2);
    memcpy(&ub, &b, 2);
    return (uint32_t)ua | ((uint32_t)ub << 16);
}

// ---------------------------------------------------------------------------
// CSR build (unchanged from R3)
// ---------------------------------------------------------------------------
__global__ void zero_cnt_kernel(int n) {
    int i = blockIdx.x * blockDim.x + threadIdx.x;
    if (i < n) g_cnt[i] = 0;
}

__global__ void count_kernel(const int* __restrict__ ed, int E) {
    int e = blockIdx.x * blockDim.x + threadIdx.x;
    if (e < E) atomicAdd(&g_cnt[ed[e]], 1);
}

__device__ __forceinline__ int warp_incl_scan(int v, int lane) {
#pragma unroll
    for (int o = 1; o < 32; o <<= 1) {
        int t = __shfl_up_sync(0xFFFFFFFFu, v, o);
        if (lane >= o) v += t;
    }
    return v;
}

__global__ void __launch_bounds__(SCAN_B) scan1_kernel(int n) {
    __shared__ int wsum[SCAN_B / 32];
    int tid = threadIdx.x, lane = tid & 31, wid = tid >> 5;
    int i = blockIdx.x * SCAN_B + tid;
    int v = (i < n) ? g_cnt[i] : 0;
#pragma unroll
    for (int o = 16; o; o >>= 1) v += __shfl_xor_sync(0xFFFFFFFFu, v, o);
    if (lane == 0) wsum[wid] = v;
    __syncthreads();
    if (wid == 0) {
        int s = (lane < SCAN_B / 32) ? wsum[lane] : 0;
#pragma unroll
        for (int o = 16; o; o >>= 1) s += __shfl_xor_sync(0xFFFFFFFFu, s, o);
        if (lane == 0) g_part[blockIdx.x] = s;
    }
}

__global__ void scan2_kernel(int nb, int n, int E) {
    __shared__ int sh[128];
    int tid = threadIdx.x;
    int v = (tid < nb) ? g_part[tid] : 0;
    sh[tid] = v;
    __syncthreads();
#pragma unroll
    for (int o = 1; o < 128; o <<= 1) {
        int t = (tid >= o) ? sh[tid - o] : 0;
        __syncthreads();
        sh[tid] += t;
        __syncthreads();
    }
    if (tid < nb) g_part[tid] = sh[tid] - v;
    if (tid == 0) g_off[n] = E;
}

__global__ void __launch_bounds__(SCAN_B) scan3_kernel(int n) {
    __shared__ int wsum[SCAN_B / 32];
    int tid = threadIdx.x, lane = tid & 31, wid = tid >> 5;
    int i = blockIdx.x * SCAN_B + tid;
    int v = (i < n) ? g_cnt[i] : 0;
    int incl = warp_incl_scan(v, lane);
    if (lane == 31) wsum[wid] = incl;
    __syncthreads();
    if (wid == 0) {
        int s = (lane < SCAN_B / 32) ? wsum[lane] : 0;
        int si = warp_incl_scan(s, lane);
        if (lane < SCAN_B / 32) wsum[lane] = si - s;
    }
    __syncthreads();
    int excl = incl - v + wsum[wid] + g_part[blockIdx.x];
    if (i < n) { g_off[i] = excl; g_cur[i] = excl; }
}

__global__ void scatter_kernel(const int* __restrict__ es,
                               const int* __restrict__ ed, int E) {
    int e = blockIdx.x * blockDim.x + threadIdx.x;
    if (e < E) {
        int pos = atomicAdd(&g_cur[ed[e]], 1);
        g_srcs[pos] = es[e];
    }
}

// ---------------------------------------------------------------------------
// HMMA bf16 split GEMM (mma.sync m16n8k16, sm_80+ path -- works on sm_100):
//   C[m, n] = act( sum_k A[m,k] * W[n, wbase+k] + bias[n] ),  n in [0,128)
//   fp32 -> (hi, lo) bf16; D += Ah*Bh + Al*Bh + Ah*Bl  (fp32 reg accumulate)
// Block: 256 threads = 8 warps (4 M x 2 N), tile 128(M) x 128(N), warp tile
// 32x64. K chunked by 64. SMEM tiles padded to 72 bf16/row (144B, conflict-
// free for ldmatrix: row stride = 36 words -> 4-bank stagger per row).
// ---------------------------------------------------------------------------
#define LDSB   144                 // bytes per smem tile row (72 bf16)
#define TILEB  (128 * LDSB)        // 18432
#define OFF_AH 0
#define OFF_AL TILEB
#define OFF_BH (2 * TILEB)
#define OFF_BL (3 * TILEB)
#define SMEM_SZ (4 * TILEB)        // 73728

template <bool TWO, bool RELU>
__global__ void __launch_bounds__(256) mma_gemm_kernel(
    const float* __restrict__ A1,
    const float* __restrict__ A2,
    const float* __restrict__ W, int ldw, int wbase,
    const float* __restrict__ bias,
    float* __restrict__ C, int M)
{
    extern __shared__ char smem[];
    const uint32_t sb = s2u(smem);
    const int tid  = threadIdx.x;
    const int warp = tid >> 5;
    const int lane = tid & 31;
    const int wm   = (warp & 3) * 32;   // warp M offset in tile
    const int wn   = (warp >> 2) * 64;  // warp N offset in tile
    const int m0   = blockIdx.x * 128;

    float acc[2][8][4];
#pragma unroll
    for (int mf = 0; mf < 2; mf++)
#pragma unroll
        for (int nf = 0; nf < 8; nf++)
#pragma unroll
            for (int j = 0; j < 4; j++) acc[mf][nf][j] = 0.0f;

    const int nch = TWO ? 4 : 2;
    for (int ch = 0; ch < nch; ch++) {
        const float* Ap = (TWO && ch >= 2) ? A2 : A1;
        const int ak0 = TWO ? ((ch & 1) * 64) : ch * 64;
        const int wk0 = wbase + ch * 64;

        if (ch > 0) __syncthreads();   // previous mma reads done

        // --- convert A tile: 128 rows x 64 cols fp32 -> bf16 hi/lo ---
#pragma unroll
        for (int t = 0; t < 8; t++) {
            int slot = tid + t * 256;        // 0..2047 float4 slots
            int row  = slot >> 4;            // 0..127
            int c4   = slot & 15;            // col = c4*4
            int m = m0 + row;
            if (m >= M) m = M - 1;
            float4 v = *(const float4*)(Ap + (size_t)m * D + ak0 + c4 * 4);
            __nv_bfloat16 h0 = __float2bfloat16_rn(v.x);
            __nv_bfloat16 h1 = __float2bfloat16_rn(v.y);
            __nv_bfloat16 h2 = __float2bfloat16_rn(v.z);
            __nv_bfloat16 h3 = __float2bfloat16_rn(v.w);
            uint32_t off = row * LDSB + c4 * 8;
            *(uint2*)(smem + OFF_AH + off) =
                make_uint2(pack2h(h0, h1), pack2h(h2, h3));
            *(uint2*)(smem + OFF_AL + off) =
                make_uint2(pack_bf16(v.x - __bfloat162float(h0), v.y - __bfloat162float(h1)),
                           pack_bf16(v.z - __bfloat162float(h2), v.w - __bfloat162float(h3)));
        }
        // --- convert B tile: W rows n=0..127, cols wk0..wk0+63 ---
#pragma unroll
        for (int t = 0; t < 8; t++) {
            int slot = tid + t * 256;
            int row  = slot >> 4;
            int c4   = slot & 15;
            float4 v = *(const float4*)(W + (size_t)row * ldw + wk0 + c4 * 4);
            __nv_bfloat16 h0 = __float2bfloat16_rn(v.x);
            __nv_bfloat16 h1 = __float2bfloat16_rn(v.y);
            __nv_bfloat16 h2 = __float2bfloat16_rn(v.z);
            __nv_bfloat16 h3 = __float2bfloat16_rn(v.w);
            uint32_t off = row * LDSB + c4 * 8;
            *(uint2*)(smem + OFF_BH + off) =
                make_uint2(pack2h(h0, h1), pack2h(h2, h3));
            *(uint2*)(smem + OFF_BL + off) =
                make_uint2(pack_bf16(v.x - __bfloat162float(h0), v.y - __bfloat162float(h1)),
                           pack_bf16(v.z - __bfloat162float(h2), v.w - __bfloat162float(h3)));
        }
        __syncthreads();

        // --- mma over 4 k16-steps ---
#pragma unroll
        for (int ks = 0; ks < 4; ks++) {
            uint32_t ah[2][4], al[2][4];
            {
                // A frag: matrices (m0-7,k0-7),(m8-15,k0-7),(m0-7,k8-15),(m8-15,k8-15)
                uint32_t off = (uint32_t)(wm + (lane & 15)) * LDSB
                             + (ks * 16 + (lane >> 4) * 8) * 2;
#pragma unroll
                for (int mf = 0; mf < 2; mf++) {
                    ldsm_x4(ah[mf], sb + OFF_AH + off + mf * 16 * LDSB);
                    ldsm_x4(al[mf], sb + OFF_AL + off + mf * 16 * LDSB);
                }
            }
            // B frags: p covers n-rows [wn+p*16, wn+p*16+16) = nf pair (2p, 2p+1)
            // matrices: (n0-7,k0-7),(n0-7,k8-15),(n8-15,k0-7),(n8-15,k8-15)
            uint32_t boff;
            {
                int i = lane >> 3;                    // 0..3 matrix index
                int r = (i >> 1) * 8 + (lane & 7);    // n row within 16
                int h = i & 1;                        // k half
                boff = (uint32_t)(wn + r) * LDSB + (ks * 16 + h * 8) * 2;
            }
#pragma unroll
            for (int p = 0; p < 4; p++) {
                uint32_t bh[4], bl[4];
                ldsm_x4(bh, sb + OFF_BH + boff + p * 16 * LDSB);
                ldsm_x4(bl, sb + OFF_BL + boff + p * 16 * LDSB);
#pragma unroll
                for (int mf = 0; mf < 2; mf++) {
                    mma16816(acc[mf][2 * p],     ah[mf], &bh[0]);
                    mma16816(acc[mf][2 * p + 1], ah[mf], &bh[2]);
                    mma16816(acc[mf][2 * p],     al[mf], &bh[0]);
                    mma16816(acc[mf][2 * p + 1], al[mf], &bh[2]);
                    mma16816(acc[mf][2 * p],     ah[mf], &bl[0]);
                    mma16816(acc[mf][2 * p + 1], ah[mf], &bl[2]);
                }
            }
        }
    }

    // --- epilogue: c0,c1 -> (m = lane/4, n = 2*(lane%4)+{0,1}); c2,c3 -> m+8 ---
#pragma unroll
    for (int mf = 0; mf < 2; mf++) {
#pragma unroll
        for (int nf = 0; nf < 8; nf++) {
            int n = wn + nf * 8 + (lane & 3) * 2;
            float bx = 0.f, by = 0.f;
            if (bias) {
                float2 bv = *(const float2*)(bias + n);
                bx = bv.x; by = bv.y;
            }
            int mrow = m0 + wm + mf * 16 + (lane >> 2);
            float* c = acc[mf][nf];
            if (mrow < M) {
                float ox = c[0] + bx, oy = c[1] + by;
                if (RELU) { ox = fmaxf(ox, 0.f); oy = fmaxf(oy, 0.f); }
                float2 o; o.x = ox; o.y = oy;
                *(float2*)(C + (size_t)mrow * D + n) = o;
            }
            if (mrow + 8 < M) {
                float ox = c[2] + bx, oy = c[3] + by;
                if (RELU) { ox = fmaxf(ox, 0.f); oy = fmaxf(oy, 0.f); }
                float2 o; o.x = ox; o.y = oy;
                *(float2*)(C + (size_t)(mrow + 8) * D + n) = o;
            }
        }
    }
}

// ---------------------------------------------------------------------------
// Fused attention (unchanged from R3): one warp per dst, single CSR pass.
// ---------------------------------------------------------------------------
__global__ void __launch_bounds__(256) fused_attn_kernel(
    const float* __restrict__ feat_src,
    const float* __restrict__ W2,
    const float* __restrict__ b2,
    int ndst)
{
    int w    = (blockIdx.x * blockDim.x + threadIdx.x) >> 5;
    int lane = threadIdx.x & 31;
    if (w >= ndst) return;

    int beg = g_off[w];
    int end = g_off[w + 1];
    float4* nrow = (float4*)(g_neigh + (size_t)w * D);

    if (beg == end) {
        nrow[lane] = make_float4(0.f, 0.f, 0.f, 0.f);
        return;
    }

    float4 ad = ((const float4*)(g_a_dst + (size_t)w * D))[lane];
    float4 w2 = ((const float4*)W2)[lane];
    float b2v = b2[0];

    float denom = 0.0f;
    float4 acc = make_float4(0.f, 0.f, 0.f, 0.f);

    int s = __ldg(&g_srcs[beg]);
    for (int i = beg; i < end; i++) {
        int s_next = (i + 1 < end) ? __ldg(&g_srcs[i + 1]) : 0;
        float4 bs = ((const float4*)(g_b_src + (size_t)s * D))[lane];
        float4 m  = ((const float4*)(feat_src + (size_t)s * D))[lane];

        float p = tanha(ad.x + bs.x) * w2.x
                + tanha(ad.y + bs.y) * w2.y
                + tanha(ad.z + bs.z) * w2.z
                + tanha(ad.w + bs.w) * w2.w;
#pragma unroll
        for (int o = 16; o; o >>= 1) p += __shfl_xor_sync(0xFFFFFFFFu, p, o);

        float ex = __expf(p + b2v);
        denom += ex;
        acc.x = fmaf(ex, m.x, acc.x);
        acc.y = fmaf(ex, m.y, acc.y);
        acc.z = fmaf(ex, m.z, acc.z);
        acc.w = fmaf(ex, m.w, acc.w);
        s = s_next;
    }

    float inv = 1.0f / denom;
    acc.x *= inv; acc.y *= inv; acc.z *= inv; acc.w *= inv;
    nrow[lane] = acc;
}

// ---------------------------------------------------------------------------
// Launcher
// ---------------------------------------------------------------------------
extern "C" void kernel_launch(void* const* d_in, const int* in_sizes, int n_in,
                              void* d_out, int out_size)
{
    const float* feat_src = (const float*)d_in[0];
    const float* feat_dst = (const float*)d_in[1];
    const float* W1       = (const float*)d_in[2];
    const float* b1       = (const float*)d_in[3];
    const float* W2       = (const float*)d_in[4];
    const float* b2       = (const float*)d_in[5];
    const float* Wfc      = (const float*)d_in[6];
    const float* bfc      = (const float*)d_in[7];
    const int*   es       = (const int*)d_in[8];
    const int*   ed       = (const int*)d_in[9];

    const int NSRC = in_sizes[0] / D;
    const int NDST = in_sizes[1] / D;
    const int E    = in_sizes[8];
    float* out = (float*)d_out;

    void *p_a, *p_b, *p_n;
    cudaGetSymbolAddress(&p_a, g_a_dst);
    cudaGetSymbolAddress(&p_b, g_b_src);
    cudaGetSymbolAddress(&p_n, g_neigh);
    float* a_dst = (float*)p_a;
    float* b_src = (float*)p_b;
    float* neigh = (float*)p_n;

    cudaFuncSetAttribute(mma_gemm_kernel<false, false>,
                         cudaFuncAttributeMaxDynamicSharedMemorySize, SMEM_SZ);
    cudaFuncSetAttribute(mma_gemm_kernel<true, true>,
                         cudaFuncAttributeMaxDynamicSharedMemorySize, SMEM_SZ);

    // --- CSR build ---
    zero_cnt_kernel<<<(NDST + 255) / 256, 256>>>(NDST);
    count_kernel<<<(E + 255) / 256, 256>>>(ed, E);
    int nb = (NDST + SCAN_B - 1) / SCAN_B;
    scan1_kernel<<<nb, SCAN_B>>>(NDST);
    scan2_kernel<<<1, 128>>>(nb, NDST, E);
    scan3_kernel<<<nb, SCAN_B>>>(NDST);
    scatter_kernel<<<(E + 255) / 256, 256>>>(es, ed, E);

    // --- node GEMMs (HMMA bf16 split) ---
    mma_gemm_kernel<false, false><<<(NDST + 127) / 128, 256, SMEM_SZ>>>(
        feat_dst, nullptr, W1, 2 * D, 0, b1, a_dst, NDST);
    mma_gemm_kernel<false, false><<<(NSRC + 127) / 128, 256, SMEM_SZ>>>(
        feat_src, nullptr, W1, 2 * D, D, nullptr, b_src, NSRC);

    // --- fused edge softmax + aggregation ---
    fused_attn_kernel<<<(NDST * 32 + 255) / 256, 256>>>(feat_src, W2, b2, NDST);

    // --- out = relu( [feat_dst, neigh] @ Wfc^T + bfc ) ---
    mma_gemm_kernel<true, true><<<(NDST + 127) / 128, 256, SMEM_SZ>>>(
        feat_dst, neigh, Wfc, 2 * D, 0, bfc, out, NDST);
}

// round 11
// speedup vs baseline: 1.7025x; 1.1003x over previous
#include <cuda_runtime.h>
#include <cuda_bf16.h>
#include <cstdint>
#include <cstring>
#include <math.h>

#define D 128
#define MAX_NDST 50000
#define MAX_NSRC 100000
#define MAX_E    600000
#define SCAN_B   512

// Scratch (static device globals -- no allocation allowed)
__device__ __align__(16) float g_a_dst[MAX_NDST * D];   // feat_dst @ W1[:, :128]^T + b1
__device__ __align__(16) float g_b_src[MAX_NSRC * D];   // feat_src @ W1[:, 128:]^T
__device__ __align__(16) float g_neigh[MAX_NDST * D];   // softmax-weighted aggregation
__device__ __align__(16) __nv_bfloat16 g_wh[2 * 128 * 256];  // W1|Wfc hi bf16
__device__ __align__(16) __nv_bfloat16 g_wl[2 * 128 * 256];  // W1|Wfc lo bf16
__device__ int g_cnt[MAX_NDST];
__device__ int g_off[MAX_NDST + 1];
__device__ int g_cur[MAX_NDST];
__device__ int g_srcs[MAX_E];
__device__ int g_part[256];

// ---------------------------------------------------------------------------
// helpers
// ---------------------------------------------------------------------------
__device__ __forceinline__ float tanha(float x) {
    float y;
    asm("tanh.approx.f32 %0, %1;" : "=f"(y) : "f"(x));
    return y;
}

__device__ __forceinline__ uint32_t s2u(const void* p) {
    uint32_t a;
    asm("{ .reg .u64 t; cvta.to.shared.u64 t, %1; cvt.u32.u64 %0, t; }"
        : "=r"(a) : "l"(p));
    return a;
}

__device__ __forceinline__ void ldsm_x4(uint32_t* r, uint32_t addr) {
    asm volatile("ldmatrix.sync.aligned.m8n8.x4.shared.b16 {%0,%1,%2,%3}, [%4];"
        : "=r"(r[0]), "=r"(r[1]), "=r"(r[2]), "=r"(r[3]) : "r"(addr));
}

// D[16x8] += A[16x16] * B[16x8] (bf16 in, fp32 acc)
__device__ __forceinline__ void mma16816(float* c, const uint32_t* a, const uint32_t* b) {
    asm volatile("mma.sync.aligned.m16n8k16.row.col.f32.bf16.bf16.f32 "
        "{%0,%1,%2,%3}, {%4,%5,%6,%7}, {%8,%9}, {%0,%1,%2,%3};"
        : "+f"(c[0]), "+f"(c[1]), "+f"(c[2]), "+f"(c[3])
        : "r"(a[0]), "r"(a[1]), "r"(a[2]), "r"(a[3]), "r"(b[0]), "r"(b[1]));
}

__device__ __forceinline__ uint32_t pack_bf16(float a, float b) {
    __nv_bfloat162 t = __floats2bfloat162_rn(a, b);
    uint32_t r;
    memcpy(&r, &t, 4);
    return r;
}

__device__ __forceinline__ uint32_t pack2h(__nv_bfloat16 a, __nv_bfloat16 b) {
    uint16_t ua, ub;
    memcpy(&ua, &a, 2);
    memcpy(&ub, &b, 2);
    return (uint32_t)ua | ((uint32_t)ub << 16);
}

// ---------------------------------------------------------------------------
// W precompute: fp32 -> bf16 (hi, lo) for W1 and Wfc (128x256 each)
// ---------------------------------------------------------------------------
__global__ void convert_w_kernel(const float* __restrict__ W1,
                                 const float* __restrict__ Wfc) {
    int i = blockIdx.x * blockDim.x + threadIdx.x;     // 0 .. 65535
    if (i >= 2 * 128 * 256) return;
    float w = (i < 128 * 256) ? W1[i] : Wfc[i - 128 * 256];
    __nv_bfloat16 h = __float2bfloat16_rn(w);
    g_wh[i] = h;
    g_wl[i] = __float2bfloat16_rn(w - __bfloat162float(h));
}

// ---------------------------------------------------------------------------
// CSR build (unchanged from R3)
// ---------------------------------------------------------------------------
__global__ void zero_cnt_kernel(int n) {
    int i = blockIdx.x * blockDim.x + threadIdx.x;
    if (i < n) g_cnt[i] = 0;
}

__global__ void count_kernel(const int* __restrict__ ed, int E) {
    int e = blockIdx.x * blockDim.x + threadIdx.x;
    if (e < E) atomicAdd(&g_cnt[ed[e]], 1);
}

__device__ __forceinline__ int warp_incl_scan(int v, int lane) {
#pragma unroll
    for (int o = 1; o < 32; o <<= 1) {
        int t = __shfl_up_sync(0xFFFFFFFFu, v, o);
        if (lane >= o) v += t;
    }
    return v;
}

__global__ void __launch_bounds__(SCAN_B) scan1_kernel(int n) {
    __shared__ int wsum[SCAN_B / 32];
    int tid = threadIdx.x, lane = tid & 31, wid = tid >> 5;
    int i = blockIdx.x * SCAN_B + tid;
    int v = (i < n) ? g_cnt[i] : 0;
#pragma unroll
    for (int o = 16; o; o >>= 1) v += __shfl_xor_sync(0xFFFFFFFFu, v, o);
    if (lane == 0) wsum[wid] = v;
    __syncthreads();
    if (wid == 0) {
        int s = (lane < SCAN_B / 32) ? wsum[lane] : 0;
#pragma unroll
        for (int o = 16; o; o >>= 1) s += __shfl_xor_sync(0xFFFFFFFFu, s, o);
        if (lane == 0) g_part[blockIdx.x] = s;
    }
}

__global__ void scan2_kernel(int nb, int n, int E) {
    __shared__ int sh[128];
    int tid = threadIdx.x;
    int v = (tid < nb) ? g_part[tid] : 0;
    sh[tid] = v;
    __syncthreads();
#pragma unroll
    for (int o = 1; o < 128; o <<= 1) {
        int t = (tid >= o) ? sh[tid - o] : 0;
        __syncthreads();
        sh[tid] += t;
        __syncthreads();
    }
    if (tid < nb) g_part[tid] = sh[tid] - v;
    if (tid == 0) g_off[n] = E;
}

__global__ void __launch_bounds__(SCAN_B) scan3_kernel(int n) {
    __shared__ int wsum[SCAN_B / 32];
    int tid = threadIdx.x, lane = tid & 31, wid = tid >> 5;
    int i = blockIdx.x * SCAN_B + tid;
    int v = (i < n) ? g_cnt[i] : 0;
    int incl = warp_incl_scan(v, lane);
    if (lane == 31) wsum[wid] = incl;
    __syncthreads();
    if (wid == 0) {
        int s = (lane < SCAN_B / 32) ? wsum[lane] : 0;
        int si = warp_incl_scan(s, lane);
        if (lane < SCAN_B / 32) wsum[lane] = si - s;
    }
    __syncthreads();
    int excl = incl - v + wsum[wid] + g_part[blockIdx.x];
    if (i < n) { g_off[i] = excl; g_cur[i] = excl; }
}

__global__ void scatter_kernel(const int* __restrict__ es,
                               const int* __restrict__ ed, int E) {
    int e = blockIdx.x * blockDim.x + threadIdx.x;
    if (e < E) {
        int pos = atomicAdd(&g_cur[ed[e]], 1);
        g_srcs[pos] = es[e];
    }
}

// ---------------------------------------------------------------------------
// HMMA bf16 split GEMM (mma.sync m16n8k16):
//   C[m, n] = act( sum_k A[m,k] * W[n, wbase+k] + bias[n] ),  n in [0,128)
//   A: fp32 -> (hi, lo) bf16 per block; W: precomputed bf16 (Wh, Wl).
//   D += Ah*Bh + Al*Bh + Ah*Bl  (fp32 reg accumulate)
// Block: 256 threads = 8 warps (4 M x 2 N), tile 128(M) x 128(N), warp tile
// 32x64. K chunked by 64. SMEM tiles padded to 72 bf16/row (144B).
// ---------------------------------------------------------------------------
#define LDSB   144                 // bytes per smem tile row (72 bf16)
#define TILEB  (128 * LDSB)        // 18432
#define OFF_AH 0
#define OFF_AL TILEB
#define OFF_BH (2 * TILEB)
#define OFF_BL (3 * TILEB)
#define SMEM_SZ (4 * TILEB)        // 73728

template <bool TWO, bool RELU>
__global__ void __launch_bounds__(256) mma_gemm_kernel(
    const float* __restrict__ A1,
    const float* __restrict__ A2,
    const __nv_bfloat16* __restrict__ Wh,
    const __nv_bfloat16* __restrict__ Wl,
    int ldw, int wbase,
    const float* __restrict__ bias,
    float* __restrict__ C, int M)
{
    extern __shared__ char smem[];
    const uint32_t sb = s2u(smem);
    const int tid  = threadIdx.x;
    const int warp = tid >> 5;
    const int lane = tid & 31;
    const int wm   = (warp & 3) * 32;   // warp M offset in tile
    const int wn   = (warp >> 2) * 64;  // warp N offset in tile
    const int m0   = blockIdx.x * 128;

    float acc[2][8][4];
#pragma unroll
    for (int mf = 0; mf < 2; mf++)
#pragma unroll
        for (int nf = 0; nf < 8; nf++)
#pragma unroll
            for (int j = 0; j < 4; j++) acc[mf][nf][j] = 0.0f;

    const int nch = TWO ? 4 : 2;
    for (int ch = 0; ch < nch; ch++) {
        const float* Ap = (TWO && ch >= 2) ? A2 : A1;
        const int ak0 = TWO ? ((ch & 1) * 64) : ch * 64;
        const int wk0 = wbase + ch * 64;

        if (ch > 0) __syncthreads();   // previous mma reads done

        // --- convert A tile: 128 rows x 64 cols fp32 -> bf16 hi/lo ---
#pragma unroll
        for (int t = 0; t < 8; t++) {
            int slot = tid + t * 256;        // 0..2047 float4 slots
            int row  = slot >> 4;            // 0..127
            int c4   = slot & 15;            // col = c4*4
            int m = m0 + row;
            if (m >= M) m = M - 1;
            float4 v = *(const float4*)(Ap + (size_t)m * D + ak0 + c4 * 4);
            __nv_bfloat16 h0 = __float2bfloat16_rn(v.x);
            __nv_bfloat16 h1 = __float2bfloat16_rn(v.y);
            __nv_bfloat16 h2 = __float2bfloat16_rn(v.z);
            __nv_bfloat16 h3 = __float2bfloat16_rn(v.w);
            uint32_t off = row * LDSB + c4 * 8;
            *(uint2*)(smem + OFF_AH + off) =
                make_uint2(pack2h(h0, h1), pack2h(h2, h3));
            *(uint2*)(smem + OFF_AL + off) =
                make_uint2(pack_bf16(v.x - __bfloat162float(h0), v.y - __bfloat162float(h1)),
                           pack_bf16(v.z - __bfloat162float(h2), v.w - __bfloat162float(h3)));
        }
        // --- copy B tile (precomputed bf16): rows n=0..127, cols wk0..wk0+63 ---
#pragma unroll
        for (int t = 0; t < 4; t++) {
            int slot = tid + t * 256;        // 0..1023 16B slots
            int row  = slot >> 3;            // 0..127
            int c8   = slot & 7;             // col = c8*8 (8 bf16 = 16B)
            uint32_t off = row * LDSB + c8 * 16;
            *(uint4*)(smem + OFF_BH + off) =
                *(const uint4*)(Wh + (size_t)row * ldw + wk0 + c8 * 8);
            *(uint4*)(smem + OFF_BL + off) =
                *(const uint4*)(Wl + (size_t)row * ldw + wk0 + c8 * 8);
        }
        __syncthreads();

        // --- mma over 4 k16-steps ---
#pragma unroll
        for (int ks = 0; ks < 4; ks++) {
            uint32_t ah[2][4], al[2][4];
            {
                // A frag: matrices (m0-7,k0-7),(m8-15,k0-7),(m0-7,k8-15),(m8-15,k8-15)
                uint32_t off = (uint32_t)(wm + (lane & 15)) * LDSB
                             + (ks * 16 + (lane >> 4) * 8) * 2;
#pragma unroll
                for (int mf = 0; mf < 2; mf++) {
                    ldsm_x4(ah[mf], sb + OFF_AH + off + mf * 16 * LDSB);
                    ldsm_x4(al[mf], sb + OFF_AL + off + mf * 16 * LDSB);
                }
            }
            // B frags: p covers n-rows [wn+p*16, wn+p*16+16) = nf pair (2p, 2p+1)
            // matrices: (n0-7,k0-7),(n0-7,k8-15),(n8-15,k0-7),(n8-15,k8-15)
            uint32_t boff;
            {
                int i = lane >> 3;                    // 0..3 matrix index
                int r = (i >> 1) * 8 + (lane & 7);    // n row within 16
                int h = i & 1;                        // k half
                boff = (uint32_t)(wn + r) * LDSB + (ks * 16 + h * 8) * 2;
            }
#pragma unroll
            for (int p = 0; p < 4; p++) {
                uint32_t bh[4], bl[4];
                ldsm_x4(bh, sb + OFF_BH + boff + p * 16 * LDSB);
                ldsm_x4(bl, sb + OFF_BL + boff + p * 16 * LDSB);
#pragma unroll
                for (int mf = 0; mf < 2; mf++) {
                    mma16816(acc[mf][2 * p],     ah[mf], &bh[0]);
                    mma16816(acc[mf][2 * p + 1], ah[mf], &bh[2]);
                    mma16816(acc[mf][2 * p],     al[mf], &bh[0]);
                    mma16816(acc[mf][2 * p + 1], al[mf], &bh[2]);
                    mma16816(acc[mf][2 * p],     ah[mf], &bl[0]);
                    mma16816(acc[mf][2 * p + 1], ah[mf], &bl[2]);
                }
            }
        }
    }

    // --- epilogue: c0,c1 -> (m = lane/4, n = 2*(lane%4)+{0,1}); c2,c3 -> m+8 ---
#pragma unroll
    for (int mf = 0; mf < 2; mf++) {
#pragma unroll
        for (int nf = 0; nf < 8; nf++) {
            int n = wn + nf * 8 + (lane & 3) * 2;
            float bx = 0.f, by = 0.f;
            if (bias) {
                float2 bv = *(const float2*)(bias + n);
                bx = bv.x; by = bv.y;
            }
            int mrow = m0 + wm + mf * 16 + (lane >> 2);
            float* c = acc[mf][nf];
            if (mrow < M) {
                float ox = c[0] + bx, oy = c[1] + by;
                if (RELU) { ox = fmaxf(ox, 0.f); oy = fmaxf(oy, 0.f); }
                float2 o; o.x = ox; o.y = oy;
                *(float2*)(C + (size_t)mrow * D + n) = o;
            }
            if (mrow + 8 < M) {
                float ox = c[2] + bx, oy = c[3] + by;
                if (RELU) { ox = fmaxf(ox, 0.f); oy = fmaxf(oy, 0.f); }
                float2 o; o.x = ox; o.y = oy;
                *(float2*)(C + (size_t)(mrow + 8) * D + n) = o;
            }
        }
    }
}

// ---------------------------------------------------------------------------
// Fused attention (unchanged from R3): one warp per dst, single CSR pass.
// ---------------------------------------------------------------------------
__global__ void __launch_bounds__(256) fused_attn_kernel(
    const float* __restrict__ feat_src,
    const float* __restrict__ W2,
    const float* __restrict__ b2,
    int ndst)
{
    int w    = (blockIdx.x * blockDim.x + threadIdx.x) >> 5;
    int lane = threadIdx.x & 31;
    if (w >= ndst) return;

    int beg = g_off[w];
    int end = g_off[w + 1];
    float4* nrow = (float4*)(g_neigh + (size_t)w * D);

    if (beg == end) {
        nrow[lane] = make_float4(0.f, 0.f, 0.f, 0.f);
        return;
    }

    float4 ad = ((const float4*)(g_a_dst + (size_t)w * D))[lane];
    float4 w2 = ((const float4*)W2)[lane];
    float b2v = b2[0];

    float denom = 0.0f;
    float4 acc = make_float4(0.f, 0.f, 0.f, 0.f);

    int s = __ldg(&g_srcs[beg]);
    for (int i = beg; i < end; i++) {
        int s_next = (i + 1 < end) ? __ldg(&g_srcs[i + 1]) : 0;
        float4 bs = ((const float4*)(g_b_src + (size_t)s * D))[lane];
        float4 m  = ((const float4*)(feat_src + (size_t)s * D))[lane];

        float p = tanha(ad.x + bs.x) * w2.x
                + tanha(ad.y + bs.y) * w2.y
                + tanha(ad.z + bs.z) * w2.z
                + tanha(ad.w + bs.w) * w2.w;
#pragma unroll
        for (int o = 16; o; o >>= 1) p += __shfl_xor_sync(0xFFFFFFFFu, p, o);

        float ex = __expf(p + b2v);
        denom += ex;
        acc.x = fmaf(ex, m.x, acc.x);
        acc.y = fmaf(ex, m.y, acc.y);
        acc.z = fmaf(ex, m.z, acc.z);
        acc.w = fmaf(ex, m.w, acc.w);
        s = s_next;
    }

    float inv = 1.0f / denom;
    acc.x *= inv; acc.y *= inv; acc.z *= inv; acc.w *= inv;
    nrow[lane] = acc;
}

// ---------------------------------------------------------------------------
// Launcher
// ---------------------------------------------------------------------------
extern "C" void kernel_launch(void* const* d_in, const int* in_sizes, int n_in,
                              void* d_out, int out_size)
{
    const float* feat_src = (const float*)d_in[0];
    const float* feat_dst = (const float*)d_in[1];
    const float* W1       = (const float*)d_in[2];
    const float* b1       = (const float*)d_in[3];
    const float* W2       = (const float*)d_in[4];
    const float* b2       = (const float*)d_in[5];
    const float* Wfc      = (const float*)d_in[6];
    const float* bfc      = (const float*)d_in[7];
    const int*   es       = (const int*)d_in[8];
    const int*   ed       = (const int*)d_in[9];

    const int NSRC = in_sizes[0] / D;
    const int NDST = in_sizes[1] / D;
    const int E    = in_sizes[8];
    float* out = (float*)d_out;

    void *p_a, *p_b, *p_n, *p_wh, *p_wl;
    cudaGetSymbolAddress(&p_a, g_a_dst);
    cudaGetSymbolAddress(&p_b, g_b_src);
    cudaGetSymbolAddress(&p_n, g_neigh);
    cudaGetSymbolAddress(&p_wh, g_wh);
    cudaGetSymbolAddress(&p_wl, g_wl);
    float* a_dst = (float*)p_a;
    float* b_src = (float*)p_b;
    float* neigh = (float*)p_n;
    const __nv_bfloat16* wh = (const __nv_bfloat16*)p_wh;
    const __nv_bfloat16* wl = (const __nv_bfloat16*)p_wl;

    cudaFuncSetAttribute(mma_gemm_kernel<false, false>,
                         cudaFuncAttributeMaxDynamicSharedMemorySize, SMEM_SZ);
    cudaFuncSetAttribute(mma_gemm_kernel<true, true>,
                         cudaFuncAttributeMaxDynamicSharedMemorySize, SMEM_SZ);

    // --- W precompute (bf16 hi/lo) ---
    convert_w_kernel<<<(2 * 128 * 256 + 255) / 256, 256>>>(W1, Wfc);

    // --- CSR build ---
    zero_cnt_kernel<<<(NDST + 255) / 256, 256>>>(NDST);
    count_kernel<<<(E + 255) / 256, 256>>>(ed, E);
    int nb = (NDST + SCAN_B - 1) / SCAN_B;
    scan1_kernel<<<nb, SCAN_B>>>(NDST);
    scan2_kernel<<<1, 128>>>(nb, NDST, E);
    scan3_kernel<<<nb, SCAN_B>>>(NDST);
    scatter_kernel<<<(E + 255) / 256, 256>>>(es, ed, E);

    // --- node GEMMs (HMMA bf16 split, precomputed W) ---
    mma_gemm_kernel<false, false><<<(NDST + 127) / 128, 256, SMEM_SZ>>>(
        feat_dst, nullptr, wh, wl, 2 * D, 0, b1, a_dst, NDST);
    mma_gemm_kernel<false, false><<<(NSRC + 127) / 128, 256, SMEM_SZ>>>(
        feat_src, nullptr, wh, wl, 2 * D, D, nullptr, b_src, NSRC);

    // --- fused edge softmax + aggregation ---
    fused_attn_kernel<<<(NDST * 32 + 255) / 256, 256>>>(feat_src, W2, b2, NDST);

    // --- out = relu( [feat_dst, neigh] @ Wfc^T + bfc ) ---
    mma_gemm_kernel<true, true><<<(NDST + 127) / 128, 256, SMEM_SZ>>>(
        feat_dst, neigh, wh + 128 * 256, wl + 128 * 256, 2 * D, 0, bfc, out, NDST);
}